// round 12
// baseline (speedup 1.0000x reference)
#include <cuda_runtime.h>
#include <cuda_fp16.h>
#include <cuda_fp8.h>
#include <math.h>

#define N_WORDS 100000
#define N_SAMPLES 65536
#define KNEG 10
#define NTERMS (KNEG + 1)
#define DIM 128
#define WARPS_PER_BLOCK 4
#define THREADS (WARPS_PER_BLOCK * 32)
#define SAMPLES_PER_WARP 8
#define SAMPLES_PER_BLOCK (WARPS_PER_BLOCK * SAMPLES_PER_WARP)   // 32
#define NBLOCKS (N_SAMPLES / SAMPLES_PER_BLOCK)                  // 2048

// fp8(e4m3) copy of W_out, rebuilt every launch (12.8 MB scratch).
// Row layout PERMUTED: row r, uint4 #u dword #j = elements [32j+4u .. +4).
__device__ uint4         g_wout_f8[(size_t)N_WORDS * 8];
__device__ float         g_acc;      // zero at load; self-resets each run
__device__ unsigned int  g_count;    // arrival counter; self-resets each run

// fast log-sigmoid: min(x,0) - log(1 + exp(-|x|)), MUFU-based
__device__ __forceinline__ float log_sigmoid(float x) {
    float t = __expf(-fabsf(x));
    return fminf(x, 0.0f) - __logf(1.0f + t);
}

__device__ __forceinline__ float group4_sum(float v) {
    v += __shfl_xor_sync(0xFFFFFFFFu, v, 1);
    v += __shfl_xor_sync(0xFFFFFFFFu, v, 2);
    return v;
}

__device__ __forceinline__ float warp_sum(float v) {
    v += __shfl_xor_sync(0xFFFFFFFFu, v, 16);
    v += __shfl_xor_sync(0xFFFFFFFFu, v, 8);
    v += __shfl_xor_sync(0xFFFFFFFFu, v, 4);
    v += __shfl_xor_sync(0xFFFFFFFFu, v, 2);
    v += __shfl_xor_sync(0xFFFFFFFFu, v, 1);
    return v;
}

__device__ __forceinline__ __half2 fp8x2_to_h2(unsigned short s) {
    __half2_raw r = __nv_cvt_fp8x2_to_halfraw2((__nv_fp8x2_storage_t)s, __NV_E4M3);
    return *reinterpret_cast<__half2*>(&r);
}

// 16B async copy gmem -> smem, no registers consumed for the data
__device__ __forceinline__ void cp_async16(void* smem_dst, const void* gmem_src) {
    unsigned int d = (unsigned int)__cvta_generic_to_shared(smem_dst);
    asm volatile("cp.async.cg.shared.global [%0], [%1], 16;"
                 :: "r"(d), "l"(gmem_src) : "memory");
}

// ---- Kernel 1: W_out fp32 -> fp8 e4m3, permuted pack (8 threads per row) ----
#define CONV_THREADS 256
#define CONV_BLOCKS ((N_WORDS * 8) / CONV_THREADS)   // 3125

__global__ void __launch_bounds__(CONV_THREADS)
convert_wout_kernel(const float* __restrict__ W_out) {
    const int t   = blockIdx.x * CONV_THREADS + threadIdx.x;
    const int row = t >> 3;
    const int u   = t & 7;
    const float4* src = reinterpret_cast<const float4*>(W_out + (size_t)row * DIM);

    uint4 o;
    unsigned int* od = reinterpret_cast<unsigned int*>(&o);
#pragma unroll
    for (int j = 0; j < 4; j++) {
        float4 f = src[8 * j + u];
        unsigned short lo = (unsigned short)
            __nv_cvt_float2_to_fp8x2(make_float2(f.x, f.y), __NV_SATFINITE, __NV_E4M3);
        unsigned short hi = (unsigned short)
            __nv_cvt_float2_to_fp8x2(make_float2(f.z, f.w), __NV_SATFINITE, __NV_E4M3);
        od[j] = (unsigned int)lo | ((unsigned int)hi << 16);
    }
    g_wout_f8[(size_t)row * 8 + u] = o;
}

// per-lane row dot: 32 a-halves vs 32 fp8 weights in two uint4
__device__ __forceinline__ float dot_row(const __half2* ahA, const __half2* ahB,
                                         const uint4& u0, const uint4& u1) {
    const unsigned int* d0 = reinterpret_cast<const unsigned int*>(&u0);
    const unsigned int* d1 = reinterpret_cast<const unsigned int*>(&u1);
    __half2 z = __float2half2_rn(0.0f);
    __half2 a0 = z, a1 = z, a2 = z, a3 = z;
#pragma unroll
    for (int j = 0; j < 4; j++) {
        unsigned int w0 = d0[j], w1 = d1[j];
        a0 = __hfma2(ahA[2 * j + 0], fp8x2_to_h2((unsigned short)(w0 & 0xFFFFu)), a0);
        a1 = __hfma2(ahA[2 * j + 1], fp8x2_to_h2((unsigned short)(w0 >> 16)),     a1);
        a2 = __hfma2(ahB[2 * j + 0], fp8x2_to_h2((unsigned short)(w1 & 0xFFFFu)), a2);
        a3 = __hfma2(ahB[2 * j + 1], fp8x2_to_h2((unsigned short)(w1 >> 16)),     a3);
    }
    __half2 s = __hadd2(__hadd2(a0, a1), __hadd2(a2, a3));
    float2 f = __half22float2(s);
    return f.x + f.y;
}

// ---- Kernel 2: loss — cp.async-staged gathers, 4 lanes/sample ----
__global__ void __launch_bounds__(THREADS)
skipgram_loss_kernel(const int* __restrict__ input_idx,
                     const int* __restrict__ output_idx,
                     const int* __restrict__ neg_idx,
                     const float* __restrict__ W_in,
                     float* __restrict__ out) {
    // [warp][term][sample][chunk]: 4*11*8*8*16 = 45056 B
    __shared__ uint4 s_w[WARPS_PER_BLOCK][NTERMS][SAMPLES_PER_WARP][8];
    __shared__ int   s_negi[WARPS_PER_BLOCK][SAMPLES_PER_WARP * KNEG];  // 80/warp
    __shared__ int   s_outi[WARPS_PER_BLOCK][SAMPLES_PER_WARP];
    __shared__ float s_loss[SAMPLES_PER_BLOCK];

    const int tid  = threadIdx.x;
    const int warp = tid >> 5;
    const int lane = tid & 31;
    const int n0   = blockIdx.x * SAMPLES_PER_BLOCK + warp * SAMPLES_PER_WARP;

    // ---- stage this warp's indices into smem (vectorized, warp-local) ----
    if (lane < 20) {            // 80 neg ints = 20 uint4 (16B-aligned: n0*40 % 16 == 0)
        reinterpret_cast<uint4*>(s_negi[warp])[lane] =
            reinterpret_cast<const uint4*>(neg_idx + (size_t)n0 * KNEG)[lane];
    } else if (lane < 22) {     // 8 out ints = 2 uint4
        reinterpret_cast<uint4*>(s_outi[warp])[lane - 20] =
            reinterpret_cast<const uint4*>(output_idx + n0)[lane - 20];
    }
    __syncwarp();

    // ---- issue ALL 88 row copies (11 terms x 8 samples x 128B) async ----
    // per warp-instruction: 4 samples x 8 chunks of 16B
    const int c   = lane & 7;            // chunk within row
    const int ss  = lane >> 3;           // sample sub-slot 0..3
#pragma unroll
    for (int t = 0; t < NTERMS; t++) {
#pragma unroll
        for (int i = 0; i < 2; i++) {
            int s   = i * 4 + ss;
            int row = (t == 0) ? s_outi[warp][s]
                               : s_negi[warp][s * KNEG + (t - 1)];
            cp_async16(&s_w[warp][t][s][c],
                       g_wout_f8 + (size_t)row * 8 + c);
        }
    }
    asm volatile("cp.async.commit_group;" ::: "memory");

    // ---- overlap: load + convert the a-vector while copies are in flight ----
    const int grp  = lane >> 2;          // 0..7: sample within warp
    const int gl   = lane & 3;           // lane within 4-lane group
    const int sloc = warp * SAMPLES_PER_WARP + grp;
    const int n    = n0 + grp;

    const int i_in = input_idx[n];
    const float4* in_row = reinterpret_cast<const float4*>(
        W_in + (size_t)i_in * DIM);
    __half2 ahA[8], ahB[8];
#pragma unroll
    for (int j = 0; j < 4; j++) {
        float4 fA = in_row[8 * j + gl];
        float4 fB = in_row[8 * j + gl + 4];
        ahA[2 * j + 0] = __floats2half2_rn(fA.x, fA.y);
        ahA[2 * j + 1] = __floats2half2_rn(fA.z, fA.w);
        ahB[2 * j + 0] = __floats2half2_rn(fB.x, fB.y);
        ahB[2 * j + 1] = __floats2half2_rn(fB.z, fB.w);
    }

    // ---- wait for staged rows, then compute (R10 structure) ----
    asm volatile("cp.async.wait_group 0;" ::: "memory");
    __syncwarp();

    float dpos = dot_row(ahA, ahB, s_w[warp][0][grp][gl], s_w[warp][0][grp][gl + 4]);
    dpos = group4_sum(dpos);
    float loss = log_sigmoid(dpos);

    float dneg[KNEG];
#pragma unroll
    for (int k = 0; k < KNEG; k++)
        dneg[k] = dot_row(ahA, ahB, s_w[warp][k + 1][grp][gl],
                                    s_w[warp][k + 1][grp][gl + 4]);
#pragma unroll
    for (int k = 0; k < KNEG; k++) {
        float d = group4_sum(dneg[k]);
        loss += log_sigmoid(-d);
    }

    // ---- block reduce + global accumulate (last block finalizes) ----
    if (gl == 0) s_loss[sloc] = loss;
    __syncthreads();
    if (warp == 0) {
        float v = s_loss[lane];          // SAMPLES_PER_BLOCK == 32
        v = warp_sum(v);
        if (lane == 0) {
            atomicAdd(&g_acc, v);
            __threadfence();
            unsigned int arrived = atomicAdd(&g_count, 1u);
            if (arrived == NBLOCKS - 1) {
                __threadfence();
                float total = atomicExch(&g_acc, 0.0f);   // read + reset
                out[0] = total * (1.0f / (float)N_SAMPLES);
                g_count = 0u;                              // reset for replay
                __threadfence();
            }
        }
    }
}

extern "C" void kernel_launch(void* const* d_in, const int* in_sizes, int n_in,
                              void* d_out, int out_size) {
    const int*   input_idx  = (const int*)d_in[0];
    const int*   output_idx = (const int*)d_in[1];
    const int*   neg_idx    = (const int*)d_in[2];
    const float* W_in       = (const float*)d_in[3];
    const float* W_out      = (const float*)d_in[4];
    float*       out        = (float*)d_out;

    convert_wout_kernel<<<CONV_BLOCKS, CONV_THREADS>>>(W_out);
    skipgram_loss_kernel<<<NBLOCKS, THREADS>>>(input_idx, output_idx, neg_idx,
                                               W_in, out);
}

// round 13
// speedup vs baseline: 1.0809x; 1.0809x over previous
#include <cuda_runtime.h>
#include <cuda_fp16.h>
#include <cuda_fp8.h>
#include <math.h>

#define N_WORDS 100000
#define N_SAMPLES 65536
#define KNEG 10
#define NTERMS (KNEG + 1)
#define DIM 128
#define WARPS_PER_BLOCK 8
#define THREADS (WARPS_PER_BLOCK * 32)
#define SAMPLES_PER_WARP 8
#define SAMPLES_PER_BLOCK (WARPS_PER_BLOCK * SAMPLES_PER_WARP)   // 64
#define NUM_BATCHES (N_SAMPLES / SAMPLES_PER_BLOCK)              // 1024
#define LOSS_BLOCKS 592                                          // 4 per SM, 1 wave

// fp8(e4m3) copy of W_out, rebuilt every launch (12.8 MB scratch).
// Row layout PERMUTED: row r, uint4 #u dword #j = elements [32j+4u .. +4).
__device__ uint4         g_wout_f8[(size_t)N_WORDS * 8];
__device__ float         g_acc;      // zero at load; self-resets each run
__device__ unsigned int  g_count;    // arrival counter; self-resets each run

// fast log-sigmoid: min(x,0) - log(1 + exp(-|x|)), MUFU-based
__device__ __forceinline__ float log_sigmoid(float x) {
    float t = __expf(-fabsf(x));
    return fminf(x, 0.0f) - __logf(1.0f + t);
}

// sum across an aligned 4-lane group (replicated result)
__device__ __forceinline__ float group4_sum(float v) {
    v += __shfl_xor_sync(0xFFFFFFFFu, v, 1);
    v += __shfl_xor_sync(0xFFFFFFFFu, v, 2);
    return v;
}

__device__ __forceinline__ float warp_sum(float v) {
    v += __shfl_xor_sync(0xFFFFFFFFu, v, 16);
    v += __shfl_xor_sync(0xFFFFFFFFu, v, 8);
    v += __shfl_xor_sync(0xFFFFFFFFu, v, 4);
    v += __shfl_xor_sync(0xFFFFFFFFu, v, 2);
    v += __shfl_xor_sync(0xFFFFFFFFu, v, 1);
    return v;
}

__device__ __forceinline__ __half2 fp8x2_to_h2(unsigned short s) {
    __half2_raw r = __nv_cvt_fp8x2_to_halfraw2((__nv_fp8x2_storage_t)s, __NV_E4M3);
    return *reinterpret_cast<__half2*>(&r);
}

// ---- Kernel 1: W_out fp32 -> fp8 e4m3, permuted pack (8 threads per row) ----
#define CONV_THREADS 256
#define CONV_BLOCKS ((N_WORDS * 8) / CONV_THREADS)   // 3125

__global__ void __launch_bounds__(CONV_THREADS)
convert_wout_kernel(const float* __restrict__ W_out) {
    const int t   = blockIdx.x * CONV_THREADS + threadIdx.x;
    const int row = t >> 3;
    const int u   = t & 7;
    const float4* src = reinterpret_cast<const float4*>(W_out + (size_t)row * DIM);

    uint4 o;
    unsigned int* od = reinterpret_cast<unsigned int*>(&o);
#pragma unroll
    for (int j = 0; j < 4; j++) {
        float4 f = src[8 * j + u];        // coalesced 128B per load across group
        unsigned short lo = (unsigned short)
            __nv_cvt_float2_to_fp8x2(make_float2(f.x, f.y), __NV_SATFINITE, __NV_E4M3);
        unsigned short hi = (unsigned short)
            __nv_cvt_float2_to_fp8x2(make_float2(f.z, f.w), __NV_SATFINITE, __NV_E4M3);
        od[j] = (unsigned int)lo | ((unsigned int)hi << 16);
    }
    g_wout_f8[(size_t)row * 8 + u] = o;
}

// per-lane row dot: 32 a-halves vs 32 fp8 weights in two uint4
__device__ __forceinline__ float dot_row(const __half2* ahA, const __half2* ahB,
                                         const uint4& u0, const uint4& u1) {
    const unsigned int* d0 = reinterpret_cast<const unsigned int*>(&u0);
    const unsigned int* d1 = reinterpret_cast<const unsigned int*>(&u1);
    __half2 z = __float2half2_rn(0.0f);
    __half2 a0 = z, a1 = z, a2 = z, a3 = z;
#pragma unroll
    for (int j = 0; j < 4; j++) {
        unsigned int w0 = d0[j], w1 = d1[j];
        a0 = __hfma2(ahA[2 * j + 0], fp8x2_to_h2((unsigned short)(w0 & 0xFFFFu)), a0);
        a1 = __hfma2(ahA[2 * j + 1], fp8x2_to_h2((unsigned short)(w0 >> 16)),     a1);
        a2 = __hfma2(ahB[2 * j + 0], fp8x2_to_h2((unsigned short)(w1 & 0xFFFFu)), a2);
        a3 = __hfma2(ahB[2 * j + 1], fp8x2_to_h2((unsigned short)(w1 >> 16)),     a3);
    }
    __half2 s = __hadd2(__hadd2(a0, a1), __hadd2(a2, a3));
    float2 f = __half22float2(s);
    return f.x + f.y;
}

// ---- Kernel 2: loss — persistent blocks, grid-stride over batches ----
__global__ void __launch_bounds__(THREADS)
skipgram_loss_kernel(const int* __restrict__ input_idx,
                     const int* __restrict__ output_idx,
                     const int* __restrict__ neg_idx,
                     const float* __restrict__ W_in,
                     float* __restrict__ out) {
    const int tid  = threadIdx.x;
    const int warp = tid >> 5;
    const int lane = tid & 31;
    const int grp  = lane >> 2;          // 0..7: sample slot within warp
    const int gl   = lane & 3;           // lane within 4-lane group
    const int sloc = warp * SAMPLES_PER_WARP + grp;   // 0..63

    float loss_acc = 0.0f;

    for (int batch = blockIdx.x; batch < NUM_BATCHES; batch += LOSS_BLOCKS) {
        const int n = batch * SAMPLES_PER_BLOCK + sloc;

        // scalar index loads (registers, broadcast within group)
        const int i_in  = input_idx[n];
        const int i_out = output_idx[n];
        const int* nrow = neg_idx + (size_t)n * KNEG;
        int nidx[KNEG];
#pragma unroll
        for (int k = 0; k < KNEG; k++) nidx[k] = nrow[k];

        // input vector: lane gl covers blocks matching uint4 #gl and #(gl+4)
        const float4* in_row = reinterpret_cast<const float4*>(
            W_in + (size_t)i_in * DIM);
        __half2 ahA[8], ahB[8];
#pragma unroll
        for (int j = 0; j < 4; j++) {
            float4 fA = in_row[8 * j + gl];
            float4 fB = in_row[8 * j + gl + 4];
            ahA[2 * j + 0] = __floats2half2_rn(fA.x, fA.y);
            ahA[2 * j + 1] = __floats2half2_rn(fA.z, fA.w);
            ahB[2 * j + 0] = __floats2half2_rn(fB.x, fB.y);
            ahB[2 * j + 1] = __floats2half2_rn(fB.z, fB.w);
        }

        // positive dot: lane loads uint4 gl and gl+4 of the row (32 B)
        float dpos;
        {
            const uint4* r = g_wout_f8 + (size_t)i_out * 8;
            uint4 u0 = r[gl];
            uint4 u1 = r[gl + 4];
            dpos = dot_row(ahA, ahB, u0, u1);
        }
        dpos = group4_sum(dpos);
        float loss = log_sigmoid(dpos);

        // negatives: flat unrolled, independent chains (ptxas batches loads)
        float dneg[KNEG];
#pragma unroll
        for (int k = 0; k < KNEG; k++) {
            const uint4* r = g_wout_f8 + (size_t)nidx[k] * 8;
            uint4 u0 = r[gl];
            uint4 u1 = r[gl + 4];
            dneg[k] = dot_row(ahA, ahB, u0, u1);
        }
#pragma unroll
        for (int k = 0; k < KNEG; k++) {
            float d = group4_sum(dneg[k]);
            loss += log_sigmoid(-d);
        }

        loss_acc += loss;                 // replicated across the 4 lanes
    }

    // block reduce (once) + global accumulate (last block finalizes)
    __shared__ float s[SAMPLES_PER_BLOCK];
    if (gl == 0) s[sloc] = loss_acc;
    __syncthreads();
    if (warp == 0) {
        float v = s[lane] + s[lane + 32];   // 64 partials -> 32
        v = warp_sum(v);
        if (lane == 0) {
            atomicAdd(&g_acc, v);
            __threadfence();
            unsigned int arrived = atomicAdd(&g_count, 1u);
            if (arrived == LOSS_BLOCKS - 1) {
                __threadfence();
                float total = atomicExch(&g_acc, 0.0f);   // read + reset
                out[0] = total * (1.0f / (float)N_SAMPLES);
                g_count = 0u;                              // reset for replay
                __threadfence();
            }
        }
    }
}

extern "C" void kernel_launch(void* const* d_in, const int* in_sizes, int n_in,
                              void* d_out, int out_size) {
    const int*   input_idx  = (const int*)d_in[0];
    const int*   output_idx = (const int*)d_in[1];
    const int*   neg_idx    = (const int*)d_in[2];
    const float* W_in       = (const float*)d_in[3];
    const float* W_out      = (const float*)d_in[4];
    float*       out        = (float*)d_out;

    convert_wout_kernel<<<CONV_BLOCKS, CONV_THREADS>>>(W_out);
    skipgram_loss_kernel<<<LOSS_BLOCKS, THREADS>>>(input_idx, output_idx, neg_idx,
                                                   W_in, out);
}

// round 14
// speedup vs baseline: 1.2326x; 1.1403x over previous
#include <cuda_runtime.h>
#include <cuda_fp16.h>
#include <cuda_fp8.h>
#include <math.h>

#define N_WORDS 100000
#define N_SAMPLES 65536
#define KNEG 10
#define NTERMS (KNEG + 1)
#define DIM 128
#define WARPS_PER_BLOCK 8
#define THREADS (WARPS_PER_BLOCK * 32)
#define SAMPLES_PER_WARP 8
#define SAMPLES_PER_BLOCK (WARPS_PER_BLOCK * SAMPLES_PER_WARP)   // 64
#define NUM_BATCHES (N_SAMPLES / SAMPLES_PER_BLOCK)              // 1024
#define LOSS_BLOCKS 592                                          // 4 per SM, 1 wave

// fp8(e4m3) copy of W_out, rebuilt every launch (12.8 MB scratch).
// Row layout PERMUTED: row r, uint4 #u dword #j = elements [32j+4u .. +4).
__device__ uint4         g_wout_f8[(size_t)N_WORDS * 8];
__device__ float         g_acc;      // zero at load; self-resets each run
__device__ unsigned int  g_count;    // arrival counter; self-resets each run

// fast log-sigmoid: min(x,0) - log(1 + exp(-|x|)), MUFU-based
__device__ __forceinline__ float log_sigmoid(float x) {
    float t = __expf(-fabsf(x));
    return fminf(x, 0.0f) - __logf(1.0f + t);
}

// sum across an aligned 4-lane group (replicated result)
__device__ __forceinline__ float group4_sum(float v) {
    v += __shfl_xor_sync(0xFFFFFFFFu, v, 1);
    v += __shfl_xor_sync(0xFFFFFFFFu, v, 2);
    return v;
}

__device__ __forceinline__ float warp_sum(float v) {
    v += __shfl_xor_sync(0xFFFFFFFFu, v, 16);
    v += __shfl_xor_sync(0xFFFFFFFFu, v, 8);
    v += __shfl_xor_sync(0xFFFFFFFFu, v, 4);
    v += __shfl_xor_sync(0xFFFFFFFFu, v, 2);
    v += __shfl_xor_sync(0xFFFFFFFFu, v, 1);
    return v;
}

__device__ __forceinline__ __half2 fp8x2_to_h2(unsigned short s) {
    __half2_raw r = __nv_cvt_fp8x2_to_halfraw2((__nv_fp8x2_storage_t)s, __NV_E4M3);
    return *reinterpret_cast<__half2*>(&r);
}

// ---- Kernel 1: W_out fp32 -> fp8 e4m3, permuted pack (8 threads per row) ----
#define CONV_THREADS 256
#define CONV_BLOCKS ((N_WORDS * 8) / CONV_THREADS)   // 3125

__global__ void __launch_bounds__(CONV_THREADS)
convert_wout_kernel(const float* __restrict__ W_out) {
    const int t   = blockIdx.x * CONV_THREADS + threadIdx.x;
    const int row = t >> 3;
    const int u   = t & 7;
    const float4* src = reinterpret_cast<const float4*>(W_out + (size_t)row * DIM);

    uint4 o;
    unsigned int* od = reinterpret_cast<unsigned int*>(&o);
#pragma unroll
    for (int j = 0; j < 4; j++) {
        float4 f = src[8 * j + u];        // coalesced 128B per load across group
        unsigned short lo = (unsigned short)
            __nv_cvt_float2_to_fp8x2(make_float2(f.x, f.y), __NV_SATFINITE, __NV_E4M3);
        unsigned short hi = (unsigned short)
            __nv_cvt_float2_to_fp8x2(make_float2(f.z, f.w), __NV_SATFINITE, __NV_E4M3);
        od[j] = (unsigned int)lo | ((unsigned int)hi << 16);
    }
    g_wout_f8[(size_t)row * 8 + u] = o;
}

// per-lane row dot: 32 a-halves vs 32 fp8 weights in two uint4
__device__ __forceinline__ float dot_row(const __half2* ahA, const __half2* ahB,
                                         const uint4& u0, const uint4& u1) {
    const unsigned int* d0 = reinterpret_cast<const unsigned int*>(&u0);
    const unsigned int* d1 = reinterpret_cast<const unsigned int*>(&u1);
    __half2 z = __float2half2_rn(0.0f);
    __half2 a0 = z, a1 = z, a2 = z, a3 = z;
#pragma unroll
    for (int j = 0; j < 4; j++) {
        unsigned int w0 = d0[j], w1 = d1[j];
        a0 = __hfma2(ahA[2 * j + 0], fp8x2_to_h2((unsigned short)(w0 & 0xFFFFu)), a0);
        a1 = __hfma2(ahA[2 * j + 1], fp8x2_to_h2((unsigned short)(w0 >> 16)),     a1);
        a2 = __hfma2(ahB[2 * j + 0], fp8x2_to_h2((unsigned short)(w1 & 0xFFFFu)), a2);
        a3 = __hfma2(ahB[2 * j + 1], fp8x2_to_h2((unsigned short)(w1 >> 16)),     a3);
    }
    __half2 s = __hadd2(__hadd2(a0, a1), __hadd2(a2, a3));
    float2 f = __half22float2(s);
    return f.x + f.y;
}

// ---- Kernel 2: loss — persistent blocks, grid-stride over batches ----
__global__ void __launch_bounds__(THREADS)
skipgram_loss_kernel(const int* __restrict__ input_idx,
                     const int* __restrict__ output_idx,
                     const int* __restrict__ neg_idx,
                     const float* __restrict__ W_in,
                     float* __restrict__ out) {
    const int tid  = threadIdx.x;
    const int warp = tid >> 5;
    const int lane = tid & 31;
    const int grp  = lane >> 2;          // 0..7: sample slot within warp
    const int gl   = lane & 3;           // lane within 4-lane group
    const int sloc = warp * SAMPLES_PER_WARP + grp;   // 0..63

    float loss_acc = 0.0f;

    for (int batch = blockIdx.x; batch < NUM_BATCHES; batch += LOSS_BLOCKS) {
        const int n = batch * SAMPLES_PER_BLOCK + sloc;

        // scalar index loads (registers, broadcast within group)
        const int i_in  = input_idx[n];
        const int i_out = output_idx[n];
        const int* nrow = neg_idx + (size_t)n * KNEG;
        int nidx[KNEG];
#pragma unroll
        for (int k = 0; k < KNEG; k++) nidx[k] = nrow[k];

        // input vector: lane gl covers blocks matching uint4 #gl and #(gl+4)
        const float4* in_row = reinterpret_cast<const float4*>(
            W_in + (size_t)i_in * DIM);
        __half2 ahA[8], ahB[8];
#pragma unroll
        for (int j = 0; j < 4; j++) {
            float4 fA = in_row[8 * j + gl];
            float4 fB = in_row[8 * j + gl + 4];
            ahA[2 * j + 0] = __floats2half2_rn(fA.x, fA.y);
            ahA[2 * j + 1] = __floats2half2_rn(fA.z, fA.w);
            ahB[2 * j + 0] = __floats2half2_rn(fB.x, fB.y);
            ahB[2 * j + 1] = __floats2half2_rn(fB.z, fB.w);
        }

        // positive dot: lane loads uint4 gl and gl+4 of the row (32 B)
        float dpos;
        {
            const uint4* r = g_wout_f8 + (size_t)i_out * 8;
            uint4 u0 = r[gl];
            uint4 u1 = r[gl + 4];
            dpos = dot_row(ahA, ahB, u0, u1);
        }
        dpos = group4_sum(dpos);
        float loss = log_sigmoid(dpos);

        // negatives: flat unrolled, independent chains (ptxas batches loads)
        float dneg[KNEG];
#pragma unroll
        for (int k = 0; k < KNEG; k++) {
            const uint4* r = g_wout_f8 + (size_t)nidx[k] * 8;
            uint4 u0 = r[gl];
            uint4 u1 = r[gl + 4];
            dneg[k] = dot_row(ahA, ahB, u0, u1);
        }
#pragma unroll
        for (int k = 0; k < KNEG; k++) {
            float d = group4_sum(dneg[k]);
            loss += log_sigmoid(-d);
        }

        loss_acc += loss;                 // replicated across the 4 lanes
    }

    // block reduce (once) + global accumulate (last block finalizes)
    __shared__ float s[SAMPLES_PER_BLOCK];
    if (gl == 0) s[sloc] = loss_acc;
    __syncthreads();
    if (warp == 0) {
        float v = s[lane] + s[lane + 32];   // 64 partials -> 32
        v = warp_sum(v);
        if (lane == 0) {
            atomicAdd(&g_acc, v);
            __threadfence();
            unsigned int arrived = atomicAdd(&g_count, 1u);
            if (arrived == LOSS_BLOCKS - 1) {
                __threadfence();
                float total = atomicExch(&g_acc, 0.0f);   // read + reset
                out[0] = total * (1.0f / (float)N_SAMPLES);
                g_count = 0u;                              // reset for replay
                __threadfence();
            }
        }
    }
}

extern "C" void kernel_launch(void* const* d_in, const int* in_sizes, int n_in,
                              void* d_out, int out_size) {
    const int*   input_idx  = (const int*)d_in[0];
    const int*   output_idx = (const int*)d_in[1];
    const int*   neg_idx    = (const int*)d_in[2];
    const float* W_in       = (const float*)d_in[3];
    const float* W_out      = (const float*)d_in[4];
    float*       out        = (float*)d_out;

    convert_wout_kernel<<<CONV_BLOCKS, CONV_THREADS>>>(W_out);
    skipgram_loss_kernel<<<LOSS_BLOCKS, THREADS>>>(input_idx, output_idx, neg_idx,
                                                   W_in, out);
}